// round 11
// baseline (speedup 1.0000x reference)
#include <cuda_runtime.h>
#include <cuda_bf16.h>
#include <cstdint>

#define BB 8
#define TT 2048
#define CC 1024
#define HH 128

// bf16 hi/lo split scratch for Q (pre-scaled), K, V
__device__ __nv_bfloat16 g_Qh[BB*TT*HH], g_Ql[BB*TT*HH];
__device__ __nv_bfloat16 g_Kh[BB*TT*HH], g_Kl[BB*TT*HH];
__device__ __nv_bfloat16 g_Vh[BB*TT*HH], g_Vl[BB*TT*HH];
// bf16 hi/lo pre-split weights: [3][1024][128]  (0=K,1=Q,2=V)
__device__ __nv_bfloat16 g_Wh[3*CC*HH], g_Wl[3*CC*HH];

// ---------------- common helpers ----------------
__device__ __forceinline__ void ldsm_x4(uint32_t& r0, uint32_t& r1,
                                        uint32_t& r2, uint32_t& r3, uint32_t a)
{
    asm volatile("ldmatrix.sync.aligned.m8n8.x4.shared.b16 {%0,%1,%2,%3}, [%4];"
                 : "=r"(r0), "=r"(r1), "=r"(r2), "=r"(r3) : "r"(a));
}
__device__ __forceinline__ void ldsm_x4t(uint32_t& r0, uint32_t& r1,
                                         uint32_t& r2, uint32_t& r3, uint32_t a)
{
    asm volatile("ldmatrix.sync.aligned.m8n8.x4.trans.shared.b16 {%0,%1,%2,%3}, [%4];"
                 : "=r"(r0), "=r"(r1), "=r"(r2), "=r"(r3) : "r"(a));
}
__device__ __forceinline__ void mma_bf16(float* d, const uint32_t* a,
                                         uint32_t b0, uint32_t b1)
{
    asm volatile("mma.sync.aligned.m16n8k16.row.col.f32.bf16.bf16.f32 "
                 "{%0,%1,%2,%3}, {%4,%5,%6,%7}, {%8,%9}, {%0,%1,%2,%3};"
                 : "+f"(d[0]), "+f"(d[1]), "+f"(d[2]), "+f"(d[3])
                 : "r"(a[0]), "r"(a[1]), "r"(a[2]), "r"(a[3]), "r"(b0), "r"(b1));
}
__device__ __forceinline__ void split2(float x, float y, uint32_t& h, uint32_t& l)
{
    __nv_bfloat162 hb = __floats2bfloat162_rn(x, y);
    __nv_bfloat162 lb = __floats2bfloat162_rn(x - __bfloat162float(hb.x),
                                              y - __bfloat162float(hb.y));
    h = *(uint32_t*)&hb;
    l = *(uint32_t*)&lb;
}
__device__ __forceinline__ void cp_async16(uint32_t dst, const void* src)
{
    asm volatile("cp.async.cg.shared.global [%0], [%1], 16;"
                 :: "r"(dst), "l"(src));
}
#define CP_COMMIT()  asm volatile("cp.async.commit_group;")
#define CP_WAIT0()   asm volatile("cp.async.wait_group 0;")
#define CP_WAIT1()   asm volatile("cp.async.wait_group 1;")

// ------------------------------------------------------------------
// Stage 0: split W into bf16 hi/lo (runs once per launch, tiny)
// ------------------------------------------------------------------
__global__ void split_w_kernel(const float* __restrict__ Wk,
                               const float* __restrict__ Wq,
                               const float* __restrict__ Wv)
{
    const float* src = (blockIdx.y == 0) ? Wk : (blockIdx.y == 1) ? Wq : Wv;
    int base = blockIdx.y * CC * HH;
    int idx = (blockIdx.x * 256 + threadIdx.x) * 4;
    float4 v = *(const float4*)&src[idx];
    uint32_t h0, l0, h1, l1;
    split2(v.x, v.y, h0, l0);
    split2(v.z, v.w, h1, l1);
    *(uint2*)&g_Wh[base + idx] = make_uint2(h0, h1);
    *(uint2*)&g_Wl[base + idx] = make_uint2(l0, l1);
}

// ------------------------------------------------------------------
// Stage 1: QKV projection, bf16 hi/lo x3, double-buffered (R7 version).
// ------------------------------------------------------------------
#define XSTRB 80
#define WSTRB 272
#define OXH 0
#define OXL (128*XSTRB)
#define OWH (2*128*XSTRB)
#define OWL (OWH + 32*WSTRB)
#define QKV_STG (OWL + 32*WSTRB)
#define QKV_SMEM (2*QKV_STG)

__global__ __launch_bounds__(256) void qkv_mma_kernel(const float* __restrict__ X)
{
    extern __shared__ __align__(16) unsigned char dsm[];
    const uint32_t sb = (uint32_t)__cvta_generic_to_shared(dsm);

    const int t    = threadIdx.x;
    const int lane = t & 31;
    const int w    = t >> 5;
    const int mw   = w >> 1;
    const int nw   = w & 1;
    const int sel  = blockIdx.y;
    const int row0 = blockIdx.x * 128;
    const int wbase = sel * CC * HH;

    float c[2][8][4];
    #pragma unroll
    for (int mf = 0; mf < 2; ++mf)
        #pragma unroll
        for (int nf = 0; nf < 8; ++nf)
            #pragma unroll
            for (int e = 0; e < 4; ++e) c[mf][nf][e] = 0.f;

    const int tQ  = lane >> 3;
    const int rAo = (lane & 7) + ((tQ & 1) << 3);
    const int cAo = tQ >> 1;
    const int rBo = (lane & 7) + ((tQ & 1) << 3);
    const int cBo = tQ >> 1;

    const int wrow = t >> 4;
    const int wc16 = t & 15;

    #pragma unroll
    for (int r = 0; r < 2; ++r) {
        int row = wrow + r * 16;
        int g = wbase + row * HH + wc16 * 8;
        cp_async16(sb + OWH + row * WSTRB + wc16 * 16, &g_Wh[g]);
        cp_async16(sb + OWL + row * WSTRB + wc16 * 16, &g_Wl[g]);
    }
    CP_COMMIT();
    #pragma unroll
    for (int r = 0; r < 4; ++r) {
        int idx = t + r * 256;
        int row = idx >> 3, c4 = idx & 7;
        float4 v = *(const float4*)&X[(size_t)(row0 + row) * CC + c4 * 4];
        uint32_t h0, l0, h1, l1;
        split2(v.x, v.y, h0, l0);
        split2(v.z, v.w, h1, l1);
        *(uint2*)(dsm + OXH + row * XSTRB + c4 * 8) = make_uint2(h0, h1);
        *(uint2*)(dsm + OXL + row * XSTRB + c4 * 8) = make_uint2(l0, l1);
    }

    for (int k0 = 0; k0 < CC; k0 += 32) {
        const int cur = (k0 >> 5) & 1;
        const uint32_t stc = sb + cur * QKV_STG;
        unsigned char* pnx = dsm + (cur ^ 1) * QKV_STG;
        const uint32_t stn = sb + (cur ^ 1) * QKV_STG;
        const bool more = (k0 + 32) < CC;

        CP_WAIT0();
        __syncthreads();

        float4 xr[4];
        if (more) {
            #pragma unroll
            for (int r = 0; r < 2; ++r) {
                int row = wrow + r * 16;
                int g = wbase + (k0 + 32 + row) * HH + wc16 * 8;
                cp_async16(stn + OWH + row * WSTRB + wc16 * 16, &g_Wh[g]);
                cp_async16(stn + OWL + row * WSTRB + wc16 * 16, &g_Wl[g]);
            }
            CP_COMMIT();
            #pragma unroll
            for (int r = 0; r < 4; ++r) {
                int idx = t + r * 256;
                int row = idx >> 3, c4 = idx & 7;
                xr[r] = *(const float4*)&X[(size_t)(row0 + row) * CC + k0 + 32 + c4 * 4];
            }
        }

        #pragma unroll
        for (int ks = 0; ks < 2; ++ks) {
            uint32_t ah[2][4], al[2][4];
            #pragma unroll
            for (int mf = 0; mf < 2; ++mf) {
                uint32_t addr = stc + (mw * 32 + mf * 16 + rAo) * XSTRB + (ks * 2 + cAo) * 16;
                ldsm_x4(ah[mf][0], ah[mf][1], ah[mf][2], ah[mf][3], addr + OXH);
                ldsm_x4(al[mf][0], al[mf][1], al[mf][2], al[mf][3], addr + OXL);
            }
            uint32_t bh[8][2], bl[8][2];
            #pragma unroll
            for (int nn = 0; nn < 4; ++nn) {
                uint32_t addr = stc + (ks * 16 + rBo) * WSTRB + (nw * 8 + nn * 2 + cBo) * 16;
                uint32_t h0, h1, h2, h3, l0_, l1_, l2_, l3_;
                ldsm_x4t(h0, h1, h2, h3, addr + OWH);
                ldsm_x4t(l0_, l1_, l2_, l3_, addr + OWL);
                bh[nn*2][0] = h0; bh[nn*2][1] = h1;
                bh[nn*2+1][0] = h2; bh[nn*2+1][1] = h3;
                bl[nn*2][0] = l0_; bl[nn*2][1] = l1_;
                bl[nn*2+1][0] = l2_; bl[nn*2+1][1] = l3_;
            }
            #pragma unroll
            for (int mf = 0; mf < 2; ++mf)
                #pragma unroll
                for (int nf = 0; nf < 8; ++nf) {
                    mma_bf16(c[mf][nf], ah[mf], bh[nf][0], bh[nf][1]);
                    mma_bf16(c[mf][nf], ah[mf], bl[nf][0], bl[nf][1]);
                    mma_bf16(c[mf][nf], al[mf], bh[nf][0], bh[nf][1]);
                }
        }

        if (more) {
            #pragma unroll
            for (int r = 0; r < 4; ++r) {
                int idx = t + r * 256;
                int row = idx >> 3, c4 = idx & 7;
                uint32_t h0, l0, h1, l1;
                split2(xr[r].x, xr[r].y, h0, l0);
                split2(xr[r].z, xr[r].w, h1, l1);
                *(uint2*)(pnx + OXH + row * XSTRB + c4 * 8) = make_uint2(h0, h1);
                *(uint2*)(pnx + OXL + row * XSTRB + c4 * 8) = make_uint2(l0, l1);
            }
        }
    }

    __nv_bfloat16 *oh, *ol;
    float sc = 1.0f;
    switch (sel) {
        case 0:  oh = g_Kh; ol = g_Kl; break;
        case 1:  oh = g_Qh; ol = g_Ql; sc = 0.08838834764831845f; break;
        default: oh = g_Vh; ol = g_Vl; break;
    }
    #pragma unroll
    for (int mf = 0; mf < 2; ++mf) {
        #pragma unroll
        for (int nf = 0; nf < 8; ++nf) {
            int row = row0 + mw * 32 + mf * 16 + (lane >> 2);
            int col = nw * 64 + nf * 8 + (lane & 3) * 2;
            uint32_t h, l;
            split2(c[mf][nf][0] * sc, c[mf][nf][1] * sc, h, l);
            *(uint32_t*)&oh[(size_t)row * HH + col] = h;
            *(uint32_t*)&ol[(size_t)row * HH + col] = l;
            split2(c[mf][nf][2] * sc, c[mf][nf][3] * sc, h, l);
            *(uint32_t*)&oh[(size_t)(row + 8) * HH + col] = h;
            *(uint32_t*)&ol[(size_t)(row + 8) * HH + col] = l;
        }
    }
}

// ------------------------------------------------------------------
// Stage 2 (v6): flash attention, bf16 hi/lo x3, 96KB smem, 2 CTAs/SM.
// K double-buffered (2 x [KH|KL] 32KB), V single buffer [VH|VL] 32KB.
// R7's LPT grid order (work-stealing balances); V(kt) issued at iter
// top, consumed after S+softmax via cheap wait_group 1.
// ------------------------------------------------------------------
#define SWZ(r,c) (((r) << 8) | ((((c) ^ ((r) & 7))) << 4))
#define KSTG 32768
#define OVH  65536
#define OVL  81920
#define ATTN_SMEM_BYTES 98304

__global__ __launch_bounds__(128, 2) void attn_kernel(float* __restrict__ out)
{
    extern __shared__ __align__(16) unsigned char smraw[];
    const int t = threadIdx.x, lane = t & 31, w = t >> 5;
    const int bid = blockIdx.x;
    const int b  = bid & 7;
    const int qt = 31 - (bid >> 3);          // global LPT order (R7)
    const int q0 = qt * 64;
    const uint32_t sb = (uint32_t)__cvta_generic_to_shared(smraw);

    // ---- prologue: K(0) into stage 0; V(0) into V buffer ----
    #pragma unroll
    for (int r = 0; r < 8; ++r) {
        int idx = t + r * 128;
        int row = idx >> 4, c = idx & 15;
        int g  = (b * TT + row) * HH + c * 8;
        int sw = SWZ(row, c);
        cp_async16(sb +         sw, &g_Kh[g]);
        cp_async16(sb + 16384 + sw, &g_Kl[g]);
    }
    CP_COMMIT();
    #pragma unroll
    for (int r = 0; r < 8; ++r) {
        int idx = t + r * 128;
        int row = idx >> 4, c = idx & 15;
        int g  = (b * TT + row) * HH + c * 8;
        int sw = SWZ(row, c);
        cp_async16(sb + OVH + sw, &g_Vh[g]);
        cp_async16(sb + OVL + sw, &g_Vl[g]);
    }
    CP_COMMIT();

    // ---- stage Q into K stage 1, extract frags ----
    #pragma unroll
    for (int r = 0; r < 8; ++r) {
        int idx = t + r * 128;
        int row = idx >> 4, c = idx & 15;
        int g = (b * TT + q0 + row) * HH + c * 8;
        *(uint4*)(smraw + KSTG +         SWZ(row, c)) = *(const uint4*)&g_Qh[g];
        *(uint4*)(smraw + KSTG + 16384 + SWZ(row, c)) = *(const uint4*)&g_Ql[g];
    }
    __syncthreads();

    uint32_t qh[8][4], ql[8][4];
    {
        int tQ  = lane >> 3;
        int rA  = w * 16 + (lane & 7) + ((tQ & 1) << 3);
        int cOf = tQ >> 1;
        #pragma unroll
        for (int ks = 0; ks < 8; ++ks) {
            int c = ks * 2 + cOf;
            ldsm_x4(qh[ks][0], qh[ks][1], qh[ks][2], qh[ks][3], sb + KSTG +         SWZ(rA, c));
            ldsm_x4(ql[ks][0], ql[ks][1], ql[ks][2], ql[ks][3], sb + KSTG + 16384 + SWZ(rA, c));
        }
    }

    float o[16][4];
    #pragma unroll
    for (int i = 0; i < 16; ++i)
        #pragma unroll
        for (int j = 0; j < 4; ++j) o[i][j] = 0.f;
    float m0 = -1e30f, m1 = -1e30f, l0 = 0.f, l1 = 0.f;

    const int tK  = lane >> 3;
    const int rB  = (lane & 7) + ((tK >> 1) << 3);
    const int cB  = tK & 1;
    const int rVo = (lane & 7) + ((tK & 1) << 3);
    const int cVo = tK >> 1;

    for (int kt = 0; kt <= qt; ++kt) {
        const uint32_t stc = sb + (uint32_t)(kt & 1) * KSTG;

        // K(kt) + V(kt-1 leftovers) complete; PV(kt-1) done by all warps.
        CP_WAIT0();
        __syncthreads();

        // issue V(kt) into the single V buffer (kt=0 preloaded)
        if (kt > 0) {
            #pragma unroll
            for (int r = 0; r < 8; ++r) {
                int idx = t + r * 128;
                int row = idx >> 4, c = idx & 15;
                int g  = (b * TT + kt * 64 + row) * HH + c * 8;
                int sw = SWZ(row, c);
                cp_async16(sb + OVH + sw, &g_Vh[g]);
                cp_async16(sb + OVL + sw, &g_Vl[g]);
            }
            CP_COMMIT();
        }
        // prefetch K(kt+1)
        if (kt < qt) {
            const uint32_t stn = sb + (uint32_t)((kt + 1) & 1) * KSTG;
            #pragma unroll
            for (int r = 0; r < 8; ++r) {
                int idx = t + r * 128;
                int row = idx >> 4, c = idx & 15;
                int g  = (b * TT + (kt + 1) * 64 + row) * HH + c * 8;
                int sw = SWZ(row, c);
                cp_async16(stn +         sw, &g_Kh[g]);
                cp_async16(stn + 16384 + sw, &g_Kl[g]);
            }
            CP_COMMIT();
        }

        // ---- S = Q K^T (3-way split MMA) ----
        float s[8][4];
        #pragma unroll
        for (int i = 0; i < 8; ++i)
            #pragma unroll
            for (int j = 0; j < 4; ++j) s[i][j] = 0.f;

        #pragma unroll
        for (int ks = 0; ks < 8; ++ks) {
            #pragma unroll
            for (int p = 0; p < 4; ++p) {
                int rr = p * 16 + rB;
                int cc = ks * 2 + cB;
                uint32_t bh0, bh1, bh2, bh3, bl0, bl1, bl2, bl3;
                ldsm_x4(bh0, bh1, bh2, bh3, stc +         SWZ(rr, cc));
                ldsm_x4(bl0, bl1, bl2, bl3, stc + 16384 + SWZ(rr, cc));
                mma_bf16(s[2*p],     qh[ks], bh0, bh1);
                mma_bf16(s[2*p],     qh[ks], bl0, bl1);
                mma_bf16(s[2*p],     ql[ks], bh0, bh1);
                mma_bf16(s[2*p + 1], qh[ks], bh2, bh3);
                mma_bf16(s[2*p + 1], qh[ks], bl2, bl3);
                mma_bf16(s[2*p + 1], ql[ks], bh2, bh3);
            }
        }

        if (kt == qt) {
            int row0 = w * 16 + (lane >> 2);
            int colb = 2 * (lane & 3);
            #pragma unroll
            for (int nf = 0; nf < 8; ++nf) {
                int cA = nf * 8 + colb;
                if (cA     > row0)     s[nf][0] = -1e30f;
                if (cA + 1 > row0)     s[nf][1] = -1e30f;
                if (cA     > row0 + 8) s[nf][2] = -1e30f;
                if (cA + 1 > row0 + 8) s[nf][3] = -1e30f;
            }
        }

        // ---- online softmax in registers ----
        float mx0 = -1e30f, mx1 = -1e30f;
        #pragma unroll
        for (int nf = 0; nf < 8; ++nf) {
            mx0 = fmaxf(mx0, fmaxf(s[nf][0], s[nf][1]));
            mx1 = fmaxf(mx1, fmaxf(s[nf][2], s[nf][3]));
        }
        mx0 = fmaxf(mx0, __shfl_xor_sync(0xffffffffu, mx0, 1));
        mx0 = fmaxf(mx0, __shfl_xor_sync(0xffffffffu, mx0, 2));
        mx1 = fmaxf(mx1, __shfl_xor_sync(0xffffffffu, mx1, 1));
        mx1 = fmaxf(mx1, __shfl_xor_sync(0xffffffffu, mx1, 2));
        float mn0 = fmaxf(m0, mx0), mn1 = fmaxf(m1, mx1);
        float a0 = __expf(m0 - mn0), a1 = __expf(m1 - mn1);
        m0 = mn0; m1 = mn1;
        float ls0 = 0.f, ls1 = 0.f;
        #pragma unroll
        for (int nf = 0; nf < 8; ++nf) {
            s[nf][0] = __expf(s[nf][0] - mn0); ls0 += s[nf][0];
            s[nf][1] = __expf(s[nf][1] - mn0); ls0 += s[nf][1];
            s[nf][2] = __expf(s[nf][2] - mn1); ls1 += s[nf][2];
            s[nf][3] = __expf(s[nf][3] - mn1); ls1 += s[nf][3];
        }
        ls0 += __shfl_xor_sync(0xffffffffu, ls0, 1);
        ls0 += __shfl_xor_sync(0xffffffffu, ls0, 2);
        ls1 += __shfl_xor_sync(0xffffffffu, ls1, 1);
        ls1 += __shfl_xor_sync(0xffffffffu, ls1, 2);
        l0 = l0 * a0 + ls0;
        l1 = l1 * a1 + ls1;

        #pragma unroll
        for (int nd = 0; nd < 16; ++nd) {
            o[nd][0] *= a0; o[nd][1] *= a0;
            o[nd][2] *= a1; o[nd][3] *= a1;
        }

        // ---- repack P (C-frag -> A-frag) with hi/lo split ----
        uint32_t ph[4][4], pl[4][4];
        #pragma unroll
        for (int kp = 0; kp < 4; ++kp) {
            int nfA = 2 * kp, nfB = 2 * kp + 1;
            split2(s[nfA][0], s[nfA][1], ph[kp][0], pl[kp][0]);
            split2(s[nfA][2], s[nfA][3], ph[kp][1], pl[kp][1]);
            split2(s[nfB][0], s[nfB][1], ph[kp][2], pl[kp][2]);
            split2(s[nfB][2], s[nfB][3], ph[kp][3], pl[kp][3]);
        }

        // wait for V(kt); leave K(kt+1) group outstanding
        if (kt < qt) { CP_WAIT1(); } else { CP_WAIT0(); }
        __syncthreads();

        // ---- O += P V (3-way split MMA) ----
        #pragma unroll
        for (int kp = 0; kp < 4; ++kp) {
            #pragma unroll
            for (int np = 0; np < 8; ++np) {
                int rV = kp * 16 + rVo;
                int cV = np * 2 + cVo;
                uint32_t vh0, vh1, vh2, vh3, vl0, vl1, vl2, vl3;
                ldsm_x4t(vh0, vh1, vh2, vh3, sb + OVH + SWZ(rV, cV));
                ldsm_x4t(vl0, vl1, vl2, vl3, sb + OVL + SWZ(rV, cV));
                mma_bf16(o[2*np],     ph[kp], vh0, vh1);
                mma_bf16(o[2*np],     ph[kp], vl0, vl1);
                mma_bf16(o[2*np],     pl[kp], vh0, vh1);
                mma_bf16(o[2*np + 1], ph[kp], vh2, vh3);
                mma_bf16(o[2*np + 1], ph[kp], vl2, vl3);
                mma_bf16(o[2*np + 1], pl[kp], vh2, vh3);
            }
        }
    }

    // ---- normalize + write ----
    {
        int grow0 = q0 + w * 16 + (lane >> 2);
        float i0 = 1.0f / l0, i1 = 1.0f / l1;
        #pragma unroll
        for (int nd = 0; nd < 16; ++nd) {
            int col = nd * 8 + 2 * (lane & 3);
            float2 v0 = make_float2(o[nd][0] * i0, o[nd][1] * i0);
            float2 v1 = make_float2(o[nd][2] * i1, o[nd][3] * i1);
            *(float2*)&out[(size_t)(b * TT + grow0) * HH + col]       = v0;
            *(float2*)&out[(size_t)(b * TT + grow0 + 8) * HH + col]   = v1;
        }
    }
}

// ------------------------------------------------------------------
extern "C" void kernel_launch(void* const* d_in, const int* in_sizes, int n_in,
                              void* d_out, int out_size)
{
    const float* x  = (const float*)d_in[0];
    const float* Wk = (const float*)d_in[1];
    const float* Wq = (const float*)d_in[2];
    const float* Wv = (const float*)d_in[3];
    float* out = (float*)d_out;

    (void)in_sizes; (void)n_in; (void)out_size;

    cudaFuncSetAttribute(qkv_mma_kernel,
                         cudaFuncAttributeMaxDynamicSharedMemorySize,
                         QKV_SMEM);
    cudaFuncSetAttribute(attn_kernel,
                         cudaFuncAttributeMaxDynamicSharedMemorySize,
                         ATTN_SMEM_BYTES);

    split_w_kernel<<<dim3(CC * HH / 4 / 256, 3), 256>>>(Wk, Wq, Wv);
    qkv_mma_kernel<<<dim3(BB * TT / 128, 3), 256, QKV_SMEM>>>(x);
    attn_kernel<<<dim3(TT / 64 * BB), 128, ATTN_SMEM_BYTES>>>(out);
}

// round 12
// speedup vs baseline: 1.0544x; 1.0544x over previous
#include <cuda_runtime.h>
#include <cuda_bf16.h>
#include <cstdint>

#define BB 8
#define TT 2048
#define CC 1024
#define HH 128

// bf16 hi/lo split scratch for Q (pre-scaled), K, V
__device__ __nv_bfloat16 g_Qh[BB*TT*HH], g_Ql[BB*TT*HH];
__device__ __nv_bfloat16 g_Kh[BB*TT*HH], g_Kl[BB*TT*HH];
__device__ __nv_bfloat16 g_Vh[BB*TT*HH], g_Vl[BB*TT*HH];
// bf16 hi/lo pre-split weights: [3][1024][128]  (0=K,1=Q,2=V)
__device__ __nv_bfloat16 g_Wh[3*CC*HH], g_Wl[3*CC*HH];

// ---------------- common helpers ----------------
__device__ __forceinline__ void ldsm_x4(uint32_t& r0, uint32_t& r1,
                                        uint32_t& r2, uint32_t& r3, uint32_t a)
{
    asm volatile("ldmatrix.sync.aligned.m8n8.x4.shared.b16 {%0,%1,%2,%3}, [%4];"
                 : "=r"(r0), "=r"(r1), "=r"(r2), "=r"(r3) : "r"(a));
}
__device__ __forceinline__ void ldsm_x4t(uint32_t& r0, uint32_t& r1,
                                         uint32_t& r2, uint32_t& r3, uint32_t a)
{
    asm volatile("ldmatrix.sync.aligned.m8n8.x4.trans.shared.b16 {%0,%1,%2,%3}, [%4];"
                 : "=r"(r0), "=r"(r1), "=r"(r2), "=r"(r3) : "r"(a));
}
__device__ __forceinline__ void mma_bf16(float* d, const uint32_t* a,
                                         uint32_t b0, uint32_t b1)
{
    asm volatile("mma.sync.aligned.m16n8k16.row.col.f32.bf16.bf16.f32 "
                 "{%0,%1,%2,%3}, {%4,%5,%6,%7}, {%8,%9}, {%0,%1,%2,%3};"
                 : "+f"(d[0]), "+f"(d[1]), "+f"(d[2]), "+f"(d[3])
                 : "r"(a[0]), "r"(a[1]), "r"(a[2]), "r"(a[3]), "r"(b0), "r"(b1));
}
__device__ __forceinline__ void split2(float x, float y, uint32_t& h, uint32_t& l)
{
    __nv_bfloat162 hb = __floats2bfloat162_rn(x, y);
    __nv_bfloat162 lb = __floats2bfloat162_rn(x - __bfloat162float(hb.x),
                                              y - __bfloat162float(hb.y));
    h = *(uint32_t*)&hb;
    l = *(uint32_t*)&lb;
}
__device__ __forceinline__ void cp_async16(uint32_t dst, const void* src)
{
    asm volatile("cp.async.cg.shared.global [%0], [%1], 16;"
                 :: "r"(dst), "l"(src));
}
#define CP_COMMIT()  asm volatile("cp.async.commit_group;")
#define CP_WAIT0()   asm volatile("cp.async.wait_group 0;")

// ------------------------------------------------------------------
// Stage 0: split W into bf16 hi/lo (runs once per launch, tiny)
// ------------------------------------------------------------------
__global__ void split_w_kernel(const float* __restrict__ Wk,
                               const float* __restrict__ Wq,
                               const float* __restrict__ Wv)
{
    const float* src = (blockIdx.y == 0) ? Wk : (blockIdx.y == 1) ? Wq : Wv;
    int base = blockIdx.y * CC * HH;
    int idx = (blockIdx.x * 256 + threadIdx.x) * 4;
    float4 v = *(const float4*)&src[idx];
    uint32_t h0, l0, h1, l1;
    split2(v.x, v.y, h0, l0);
    split2(v.z, v.w, h1, l1);
    *(uint2*)&g_Wh[base + idx] = make_uint2(h0, h1);
    *(uint2*)&g_Wl[base + idx] = make_uint2(l0, l1);
}

// ------------------------------------------------------------------
// Stage 1: QKV projection, bf16 hi/lo x3, double-buffered (R7 version).
// ------------------------------------------------------------------
#define XSTRB 80
#define WSTRB 272
#define OXH 0
#define OXL (128*XSTRB)
#define OWH (2*128*XSTRB)
#define OWL (OWH + 32*WSTRB)
#define QKV_STG (OWL + 32*WSTRB)
#define QKV_SMEM (2*QKV_STG)

__global__ __launch_bounds__(256) void qkv_mma_kernel(const float* __restrict__ X)
{
    extern __shared__ __align__(16) unsigned char dsm[];
    const uint32_t sb = (uint32_t)__cvta_generic_to_shared(dsm);

    const int t    = threadIdx.x;
    const int lane = t & 31;
    const int w    = t >> 5;
    const int mw   = w >> 1;
    const int nw   = w & 1;
    const int sel  = blockIdx.y;
    const int row0 = blockIdx.x * 128;
    const int wbase = sel * CC * HH;

    float c[2][8][4];
    #pragma unroll
    for (int mf = 0; mf < 2; ++mf)
        #pragma unroll
        for (int nf = 0; nf < 8; ++nf)
            #pragma unroll
            for (int e = 0; e < 4; ++e) c[mf][nf][e] = 0.f;

    const int tQ  = lane >> 3;
    const int rAo = (lane & 7) + ((tQ & 1) << 3);
    const int cAo = tQ >> 1;
    const int rBo = (lane & 7) + ((tQ & 1) << 3);
    const int cBo = tQ >> 1;

    const int wrow = t >> 4;
    const int wc16 = t & 15;

    #pragma unroll
    for (int r = 0; r < 2; ++r) {
        int row = wrow + r * 16;
        int g = wbase + row * HH + wc16 * 8;
        cp_async16(sb + OWH + row * WSTRB + wc16 * 16, &g_Wh[g]);
        cp_async16(sb + OWL + row * WSTRB + wc16 * 16, &g_Wl[g]);
    }
    CP_COMMIT();
    #pragma unroll
    for (int r = 0; r < 4; ++r) {
        int idx = t + r * 256;
        int row = idx >> 3, c4 = idx & 7;
        float4 v = *(const float4*)&X[(size_t)(row0 + row) * CC + c4 * 4];
        uint32_t h0, l0, h1, l1;
        split2(v.x, v.y, h0, l0);
        split2(v.z, v.w, h1, l1);
        *(uint2*)(dsm + OXH + row * XSTRB + c4 * 8) = make_uint2(h0, h1);
        *(uint2*)(dsm + OXL + row * XSTRB + c4 * 8) = make_uint2(l0, l1);
    }

    for (int k0 = 0; k0 < CC; k0 += 32) {
        const int cur = (k0 >> 5) & 1;
        const uint32_t stc = sb + cur * QKV_STG;
        unsigned char* pnx = dsm + (cur ^ 1) * QKV_STG;
        const uint32_t stn = sb + (cur ^ 1) * QKV_STG;
        const bool more = (k0 + 32) < CC;

        CP_WAIT0();
        __syncthreads();

        float4 xr[4];
        if (more) {
            #pragma unroll
            for (int r = 0; r < 2; ++r) {
                int row = wrow + r * 16;
                int g = wbase + (k0 + 32 + row) * HH + wc16 * 8;
                cp_async16(stn + OWH + row * WSTRB + wc16 * 16, &g_Wh[g]);
                cp_async16(stn + OWL + row * WSTRB + wc16 * 16, &g_Wl[g]);
            }
            CP_COMMIT();
            #pragma unroll
            for (int r = 0; r < 4; ++r) {
                int idx = t + r * 256;
                int row = idx >> 3, c4 = idx & 7;
                xr[r] = *(const float4*)&X[(size_t)(row0 + row) * CC + k0 + 32 + c4 * 4];
            }
        }

        #pragma unroll
        for (int ks = 0; ks < 2; ++ks) {
            uint32_t ah[2][4], al[2][4];
            #pragma unroll
            for (int mf = 0; mf < 2; ++mf) {
                uint32_t addr = stc + (mw * 32 + mf * 16 + rAo) * XSTRB + (ks * 2 + cAo) * 16;
                ldsm_x4(ah[mf][0], ah[mf][1], ah[mf][2], ah[mf][3], addr + OXH);
                ldsm_x4(al[mf][0], al[mf][1], al[mf][2], al[mf][3], addr + OXL);
            }
            uint32_t bh[8][2], bl[8][2];
            #pragma unroll
            for (int nn = 0; nn < 4; ++nn) {
                uint32_t addr = stc + (ks * 16 + rBo) * WSTRB + (nw * 8 + nn * 2 + cBo) * 16;
                uint32_t h0, h1, h2, h3, l0_, l1_, l2_, l3_;
                ldsm_x4t(h0, h1, h2, h3, addr + OWH);
                ldsm_x4t(l0_, l1_, l2_, l3_, addr + OWL);
                bh[nn*2][0] = h0; bh[nn*2][1] = h1;
                bh[nn*2+1][0] = h2; bh[nn*2+1][1] = h3;
                bl[nn*2][0] = l0_; bl[nn*2][1] = l1_;
                bl[nn*2+1][0] = l2_; bl[nn*2+1][1] = l3_;
            }
            #pragma unroll
            for (int mf = 0; mf < 2; ++mf)
                #pragma unroll
                for (int nf = 0; nf < 8; ++nf) {
                    mma_bf16(c[mf][nf], ah[mf], bh[nf][0], bh[nf][1]);
                    mma_bf16(c[mf][nf], ah[mf], bl[nf][0], bl[nf][1]);
                    mma_bf16(c[mf][nf], al[mf], bh[nf][0], bh[nf][1]);
                }
        }

        if (more) {
            #pragma unroll
            for (int r = 0; r < 4; ++r) {
                int idx = t + r * 256;
                int row = idx >> 3, c4 = idx & 7;
                uint32_t h0, l0, h1, l1;
                split2(xr[r].x, xr[r].y, h0, l0);
                split2(xr[r].z, xr[r].w, h1, l1);
                *(uint2*)(pnx + OXH + row * XSTRB + c4 * 8) = make_uint2(h0, h1);
                *(uint2*)(pnx + OXL + row * XSTRB + c4 * 8) = make_uint2(l0, l1);
            }
        }
    }

    __nv_bfloat16 *oh, *ol;
    float sc = 1.0f;
    switch (sel) {
        case 0:  oh = g_Kh; ol = g_Kl; break;
        case 1:  oh = g_Qh; ol = g_Ql; sc = 0.08838834764831845f; break;
        default: oh = g_Vh; ol = g_Vl; break;
    }
    #pragma unroll
    for (int mf = 0; mf < 2; ++mf) {
        #pragma unroll
        for (int nf = 0; nf < 8; ++nf) {
            int row = row0 + mw * 32 + mf * 16 + (lane >> 2);
            int col = nw * 64 + nf * 8 + (lane & 3) * 2;
            uint32_t h, l;
            split2(c[mf][nf][0] * sc, c[mf][nf][1] * sc, h, l);
            *(uint32_t*)&oh[(size_t)row * HH + col] = h;
            *(uint32_t*)&ol[(size_t)row * HH + col] = l;
            split2(c[mf][nf][2] * sc, c[mf][nf][3] * sc, h, l);
            *(uint32_t*)&oh[(size_t)(row + 8) * HH + col] = h;
            *(uint32_t*)&ol[(size_t)(row + 8) * HH + col] = l;
        }
    }
}

// ------------------------------------------------------------------
// Stage 2 (v7): flash attention, bf16 hi/lo x3, R7 pipeline structure.
// Q hi/lo lives in DEDICATED smem (not registers): -56 regs so ptxas
// can pipeline ldsm/cp.async; Q frags ldsm'd per-ks inside S loop.
// MMA issue order interleaves the two accumulators (distance-1 RAW).
// Smem 160KB: 2 stages x [KH|KL|VH|VL] (64KB) + [QH|QL] (32KB).
// ------------------------------------------------------------------
#define SWZ(r,c) (((r) << 8) | ((((c) ^ ((r) & 7))) << 4))
#define AST 65536
#define OQH 131072
#define OQL 147456
#define ATTN_SMEM_BYTES 163840

__global__ __launch_bounds__(128) void attn_kernel(float* __restrict__ out)
{
    extern __shared__ __align__(16) unsigned char smraw[];
    const int t = threadIdx.x, lane = t & 31, w = t >> 5;
    const int bid = blockIdx.x;
    const int b  = bid & 7;
    const int qt = 31 - (bid >> 3);          // global LPT order
    const int q0 = qt * 64;
    const uint32_t sb = (uint32_t)__cvta_generic_to_shared(smraw);

    // ---- prologue: issue K/V(0) into stage 0 ----
    #pragma unroll
    for (int r = 0; r < 8; ++r) {
        int idx = t + r * 128;
        int row = idx >> 4, c = idx & 15;
        int g  = (b * TT + row) * HH + c * 8;
        int sw = SWZ(row, c);
        cp_async16(sb +         sw, &g_Kh[g]);
        cp_async16(sb + 16384 + sw, &g_Kl[g]);
        cp_async16(sb + 32768 + sw, &g_Vh[g]);
        cp_async16(sb + 49152 + sw, &g_Vl[g]);
    }
    CP_COMMIT();

    // ---- stage Q into its dedicated region ----
    #pragma unroll
    for (int r = 0; r < 8; ++r) {
        int idx = t + r * 128;
        int row = idx >> 4, c = idx & 15;
        int g = (b * TT + q0 + row) * HH + c * 8;
        *(uint4*)(smraw + OQH + SWZ(row, c)) = *(const uint4*)&g_Qh[g];
        *(uint4*)(smraw + OQL + SWZ(row, c)) = *(const uint4*)&g_Ql[g];
    }
    __syncthreads();

    float o[16][4];
    #pragma unroll
    for (int i = 0; i < 16; ++i)
        #pragma unroll
        for (int j = 0; j < 4; ++j) o[i][j] = 0.f;
    float m0 = -1e30f, m1 = -1e30f, l0 = 0.f, l1 = 0.f;

    // lane decodes
    const int tQ  = lane >> 3;
    const int rA  = w * 16 + (lane & 7) + ((tQ & 1) << 3);   // Q a-frag row
    const int cOf = tQ >> 1;                                 // Q a-frag chunk
    const int rB  = (lane & 7) + ((tQ >> 1) << 3);           // K b-frag
    const int cB  = tQ & 1;
    const int rVo = (lane & 7) + ((tQ & 1) << 3);            // V b-frag (trans)
    const int cVo = tQ >> 1;

    for (int kt = 0; kt <= qt; ++kt) {
        const uint32_t stc = sb + (uint32_t)(kt & 1) * AST;

        CP_WAIT0();
        __syncthreads();

        // prefetch next K/V tile into other stage
        if (kt < qt) {
            const uint32_t stn = sb + (uint32_t)((kt + 1) & 1) * AST;
            #pragma unroll
            for (int r = 0; r < 8; ++r) {
                int idx = t + r * 128;
                int row = idx >> 4, c = idx & 15;
                int g  = (b * TT + (kt + 1) * 64 + row) * HH + c * 8;
                int sw = SWZ(row, c);
                cp_async16(stn +         sw, &g_Kh[g]);
                cp_async16(stn + 16384 + sw, &g_Kl[g]);
                cp_async16(stn + 32768 + sw, &g_Vh[g]);
                cp_async16(stn + 49152 + sw, &g_Vl[g]);
            }
            CP_COMMIT();
        }

        // ---- S = Q K^T (3-way split MMA, Q frags from smem per-ks) ----
        float s[8][4];
        #pragma unroll
        for (int i = 0; i < 8; ++i)
            #pragma unroll
            for (int j = 0; j < 4; ++j) s[i][j] = 0.f;

        #pragma unroll
        for (int ks = 0; ks < 8; ++ks) {
            uint32_t qh[4], ql[4];
            {
                int c = ks * 2 + cOf;
                ldsm_x4(qh[0], qh[1], qh[2], qh[3], sb + OQH + SWZ(rA, c));
                ldsm_x4(ql[0], ql[1], ql[2], ql[3], sb + OQL + SWZ(rA, c));
            }
            #pragma unroll
            for (int p = 0; p < 4; ++p) {
                int rr = p * 16 + rB;
                int cc = ks * 2 + cB;
                uint32_t bh0, bh1, bh2, bh3, bl0, bl1, bl2, bl3;
                ldsm_x4(bh0, bh1, bh2, bh3, stc +         SWZ(rr, cc));
                ldsm_x4(bl0, bl1, bl2, bl3, stc + 16384 + SWZ(rr, cc));
                // interleaved: distance-1 between same-accumulator MMAs;
                // per-accumulator term order unchanged (hh, hl, lh)
                mma_bf16(s[2*p],     qh, bh0, bh1);
                mma_bf16(s[2*p + 1], qh, bh2, bh3);
                mma_bf16(s[2*p],     qh, bl0, bl1);
                mma_bf16(s[2*p + 1], qh, bl2, bl3);
                mma_bf16(s[2*p],     ql, bh0, bh1);
                mma_bf16(s[2*p + 1], ql, bh2, bh3);
            }
        }

        // ---- causal mask on diagonal tile ----
        if (kt == qt) {
            int row0 = w * 16 + (lane >> 2);
            int colb = 2 * (lane & 3);
            #pragma unroll
            for (int nf = 0; nf < 8; ++nf) {
                int cA = nf * 8 + colb;
                if (cA     > row0)     s[nf][0] = -1e30f;
                if (cA + 1 > row0)     s[nf][1] = -1e30f;
                if (cA     > row0 + 8) s[nf][2] = -1e30f;
                if (cA + 1 > row0 + 8) s[nf][3] = -1e30f;
            }
        }

        // ---- online softmax in registers ----
        float mx0 = -1e30f, mx1 = -1e30f;
        #pragma unroll
        for (int nf = 0; nf < 8; ++nf) {
            mx0 = fmaxf(mx0, fmaxf(s[nf][0], s[nf][1]));
            mx1 = fmaxf(mx1, fmaxf(s[nf][2], s[nf][3]));
        }
        mx0 = fmaxf(mx0, __shfl_xor_sync(0xffffffffu, mx0, 1));
        mx0 = fmaxf(mx0, __shfl_xor_sync(0xffffffffu, mx0, 2));
        mx1 = fmaxf(mx1, __shfl_xor_sync(0xffffffffu, mx1, 1));
        mx1 = fmaxf(mx1, __shfl_xor_sync(0xffffffffu, mx1, 2));
        float mn0 = fmaxf(m0, mx0), mn1 = fmaxf(m1, mx1);
        float a0 = __expf(m0 - mn0), a1 = __expf(m1 - mn1);
        m0 = mn0; m1 = mn1;
        float ls0 = 0.f, ls1 = 0.f;
        #pragma unroll
        for (int nf = 0; nf < 8; ++nf) {
            s[nf][0] = __expf(s[nf][0] - mn0); ls0 += s[nf][0];
            s[nf][1] = __expf(s[nf][1] - mn0); ls0 += s[nf][1];
            s[nf][2] = __expf(s[nf][2] - mn1); ls1 += s[nf][2];
            s[nf][3] = __expf(s[nf][3] - mn1); ls1 += s[nf][3];
        }
        ls0 += __shfl_xor_sync(0xffffffffu, ls0, 1);
        ls0 += __shfl_xor_sync(0xffffffffu, ls0, 2);
        ls1 += __shfl_xor_sync(0xffffffffu, ls1, 1);
        ls1 += __shfl_xor_sync(0xffffffffu, ls1, 2);
        l0 = l0 * a0 + ls0;
        l1 = l1 * a1 + ls1;

        #pragma unroll
        for (int nd = 0; nd < 16; ++nd) {
            o[nd][0] *= a0; o[nd][1] *= a0;
            o[nd][2] *= a1; o[nd][3] *= a1;
        }

        // ---- repack P (C-frag -> A-frag) with hi/lo split ----
        uint32_t ph[4][4], pl[4][4];
        #pragma unroll
        for (int kp = 0; kp < 4; ++kp) {
            int nfA = 2 * kp, nfB = 2 * kp + 1;
            split2(s[nfA][0], s[nfA][1], ph[kp][0], pl[kp][0]);
            split2(s[nfA][2], s[nfA][3], ph[kp][1], pl[kp][1]);
            split2(s[nfB][0], s[nfB][1], ph[kp][2], pl[kp][2]);
            split2(s[nfB][2], s[nfB][3], ph[kp][3], pl[kp][3]);
        }

        // ---- O += P V (3-way split MMA, interleaved accumulators) ----
        #pragma unroll
        for (int kp = 0; kp < 4; ++kp) {
            #pragma unroll
            for (int np = 0; np < 8; ++np) {
                int rV = kp * 16 + rVo;
                int cV = np * 2 + cVo;
                uint32_t vh0, vh1, vh2, vh3, vl0, vl1, vl2, vl3;
                ldsm_x4t(vh0, vh1, vh2, vh3, stc + 32768 + SWZ(rV, cV));
                ldsm_x4t(vl0, vl1, vl2, vl3, stc + 49152 + SWZ(rV, cV));
                mma_bf16(o[2*np],     ph[kp], vh0, vh1);
                mma_bf16(o[2*np + 1], ph[kp], vh2, vh3);
                mma_bf16(o[2*np],     ph[kp], vl0, vl1);
                mma_bf16(o[2*np + 1], ph[kp], vl2, vl3);
                mma_bf16(o[2*np],     pl[kp], vh0, vh1);
                mma_bf16(o[2*np + 1], pl[kp], vh2, vh3);
            }
        }
    }

    // ---- normalize + write ----
    {
        int grow0 = q0 + w * 16 + (lane >> 2);
        float i0 = 1.0f / l0, i1 = 1.0f / l1;
        #pragma unroll
        for (int nd = 0; nd < 16; ++nd) {
            int col = nd * 8 + 2 * (lane & 3);
            float2 v0 = make_float2(o[nd][0] * i0, o[nd][1] * i0);
            float2 v1 = make_float2(o[nd][2] * i1, o[nd][3] * i1);
            *(float2*)&out[(size_t)(b * TT + grow0) * HH + col]       = v0;
            *(float2*)&out[(size_t)(b * TT + grow0 + 8) * HH + col]   = v1;
        }
    }
}

// ------------------------------------------------------------------
extern "C" void kernel_launch(void* const* d_in, const int* in_sizes, int n_in,
                              void* d_out, int out_size)
{
    const float* x  = (const float*)d_in[0];
    const float* Wk = (const float*)d_in[1];
    const float* Wq = (const float*)d_in[2];
    const float* Wv = (const float*)d_in[3];
    float* out = (float*)d_out;

    (void)in_sizes; (void)n_in; (void)out_size;

    cudaFuncSetAttribute(qkv_mma_kernel,
                         cudaFuncAttributeMaxDynamicSharedMemorySize,
                         QKV_SMEM);
    cudaFuncSetAttribute(attn_kernel,
                         cudaFuncAttributeMaxDynamicSharedMemorySize,
                         ATTN_SMEM_BYTES);

    split_w_kernel<<<dim3(CC * HH / 4 / 256, 3), 256>>>(Wk, Wq, Wv);
    qkv_mma_kernel<<<dim3(BB * TT / 128, 3), 256, QKV_SMEM>>>(x);
    attn_kernel<<<dim3(TT / 64 * BB), 128, ATTN_SMEM_BYTES>>>(out);
}

// round 17
// speedup vs baseline: 1.1295x; 1.0713x over previous
#include <cuda_runtime.h>
#include <cuda_bf16.h>
#include <cstdint>

#define BB 8
#define TT 2048
#define CC 1024
#define HH 128

// bf16 hi/lo split scratch for Q (pre-scaled), K, V
__device__ __nv_bfloat16 g_Qh[BB*TT*HH], g_Ql[BB*TT*HH];
__device__ __nv_bfloat16 g_Kh[BB*TT*HH], g_Kl[BB*TT*HH];
__device__ __nv_bfloat16 g_Vh[BB*TT*HH], g_Vl[BB*TT*HH];
// bf16 hi/lo pre-split weights: [3][1024][128]  (0=K,1=Q,2=V)
__device__ __nv_bfloat16 g_Wh[3*CC*HH], g_Wl[3*CC*HH];

// ---------------- common helpers ----------------
__device__ __forceinline__ void ldsm_x4(uint32_t& r0, uint32_t& r1,
                                        uint32_t& r2, uint32_t& r3, uint32_t a)
{
    asm volatile("ldmatrix.sync.aligned.m8n8.x4.shared.b16 {%0,%1,%2,%3}, [%4];"
                 : "=r"(r0), "=r"(r1), "=r"(r2), "=r"(r3) : "r"(a));
}
__device__ __forceinline__ void ldsm_x4t(uint32_t& r0, uint32_t& r1,
                                         uint32_t& r2, uint32_t& r3, uint32_t a)
{
    asm volatile("ldmatrix.sync.aligned.m8n8.x4.trans.shared.b16 {%0,%1,%2,%3}, [%4];"
                 : "=r"(r0), "=r"(r1), "=r"(r2), "=r"(r3) : "r"(a));
}
__device__ __forceinline__ void mma_bf16(float* d, const uint32_t* a,
                                         uint32_t b0, uint32_t b1)
{
    asm volatile("mma.sync.aligned.m16n8k16.row.col.f32.bf16.bf16.f32 "
                 "{%0,%1,%2,%3}, {%4,%5,%6,%7}, {%8,%9}, {%0,%1,%2,%3};"
                 : "+f"(d[0]), "+f"(d[1]), "+f"(d[2]), "+f"(d[3])
                 : "r"(a[0]), "r"(a[1]), "r"(a[2]), "r"(a[3]), "r"(b0), "r"(b1));
}
__device__ __forceinline__ void split2(float x, float y, uint32_t& h, uint32_t& l)
{
    __nv_bfloat162 hb = __floats2bfloat162_rn(x, y);
    __nv_bfloat162 lb = __floats2bfloat162_rn(x - __bfloat162float(hb.x),
                                              y - __bfloat162float(hb.y));
    h = *(uint32_t*)&hb;
    l = *(uint32_t*)&lb;
}
__device__ __forceinline__ void cp_async16(uint32_t dst, const void* src)
{
    asm volatile("cp.async.cg.shared.global [%0], [%1], 16;"
                 :: "r"(dst), "l"(src));
}
#define CP_COMMIT()  asm volatile("cp.async.commit_group;")
#define CP_WAIT0()   asm volatile("cp.async.wait_group 0;")

// ------------------------------------------------------------------
// Stage 0: split W into bf16 hi/lo (runs once per launch, tiny)
// ------------------------------------------------------------------
__global__ void split_w_kernel(const float* __restrict__ Wk,
                               const float* __restrict__ Wq,
                               const float* __restrict__ Wv)
{
    const float* src = (blockIdx.y == 0) ? Wk : (blockIdx.y == 1) ? Wq : Wv;
    int base = blockIdx.y * CC * HH;
    int idx = (blockIdx.x * 256 + threadIdx.x) * 4;
    float4 v = *(const float4*)&src[idx];
    uint32_t h0, l0, h1, l1;
    split2(v.x, v.y, h0, l0);
    split2(v.z, v.w, h1, l1);
    *(uint2*)&g_Wh[base + idx] = make_uint2(h0, h1);
    *(uint2*)&g_Wl[base + idx] = make_uint2(l0, l1);
}

// ------------------------------------------------------------------
// Stage 1 (v5b): QKV projection, bf16 hi/lo x3, double-buffered,
// N-split: each CTA does 128 rows x 64 cols -> 32 acc regs,
// ~115 regs/thread, 59KB smem -> 2 CTAs/SM (4 warps/SMSP).
// grid = (128 row-blocks, 6): sel = y>>1, nh = y&1 (column half).
// FIX vs R15: W loader now covers the full 64-col row (2 chunks/thread).
// ------------------------------------------------------------------
#define XSTRB 80     // 32 bf16 row padded to 80 B
#define WSTRB 144    // 64 bf16 row (128B) padded to 144 B
#define OXH 0
#define OXL (128*XSTRB)              // 10240
#define OWH (2*128*XSTRB)            // 20480
#define OWL (OWH + 32*WSTRB)         // 25088
#define QKV_STG (OWL + 32*WSTRB)     // 29696
#define QKV_SMEM (2*QKV_STG)         // 59392

__global__ __launch_bounds__(256, 2) void qkv_mma_kernel(const float* __restrict__ X)
{
    extern __shared__ __align__(16) unsigned char dsm[];
    const uint32_t sb = (uint32_t)__cvta_generic_to_shared(dsm);

    const int t    = threadIdx.x;
    const int lane = t & 31;
    const int w    = t >> 5;
    const int mw   = w >> 1;          // 0..3  (32-row group)
    const int nw   = w & 1;           // 0..1  (32-col group)
    const int sel  = blockIdx.y >> 1;
    const int nh   = blockIdx.y & 1;  // which 64-col half
    const int row0 = blockIdx.x * 128;
    const int wbase = sel * CC * HH + nh * 64;

    float c[2][4][4];
    #pragma unroll
    for (int mf = 0; mf < 2; ++mf)
        #pragma unroll
        for (int nf = 0; nf < 4; ++nf)
            #pragma unroll
            for (int e = 0; e < 4; ++e) c[mf][nf][e] = 0.f;

    const int tQ  = lane >> 3;
    const int rAo = (lane & 7) + ((tQ & 1) << 3);
    const int cAo = tQ >> 1;
    const int rBo = (lane & 7) + ((tQ & 1) << 3);
    const int cBo = tQ >> 1;

    // W cp.async mapping: 256 16B-chunks per hi/lo array (32 rows x 8 chunks).
    // warr: 128 threads each on hi or lo; 2 chunks per thread.
    const int warr = t >> 7;          // 0 = hi, 1 = lo
    const int wrow = (t & 127) >> 2;  // k-row 0..31
    const int wc16 = t & 3;           // base chunk 0..3 (+4 on 2nd iter)

    // ---- prologue: W(0) via cp.async, X(0) via LDG+split+STS ----
    #pragma unroll
    for (int r = 0; r < 2; ++r) {
        int ch = wc16 + r * 4;        // 16B chunk 0..7
        int g = wbase + wrow * HH + ch * 8;
        uint32_t d = sb + (warr ? OWL : OWH) + wrow * WSTRB + ch * 16;
        cp_async16(d, warr ? (const void*)&g_Wl[g] : (const void*)&g_Wh[g]);
    }
    CP_COMMIT();
    #pragma unroll
    for (int r = 0; r < 4; ++r) {
        int idx = t + r * 256;
        int row = idx >> 3, c4 = idx & 7;
        float4 v = *(const float4*)&X[(size_t)(row0 + row) * CC + c4 * 4];
        uint32_t h0, l0, h1, l1;
        split2(v.x, v.y, h0, l0);
        split2(v.z, v.w, h1, l1);
        *(uint2*)(dsm + OXH + row * XSTRB + c4 * 8) = make_uint2(h0, h1);
        *(uint2*)(dsm + OXL + row * XSTRB + c4 * 8) = make_uint2(l0, l1);
    }

    for (int k0 = 0; k0 < CC; k0 += 32) {
        const int cur = (k0 >> 5) & 1;
        const uint32_t stc = sb + cur * QKV_STG;
        unsigned char* pnx = dsm + (cur ^ 1) * QKV_STG;
        const uint32_t stn = sb + (cur ^ 1) * QKV_STG;
        const bool more = (k0 + 32) < CC;

        CP_WAIT0();
        __syncthreads();

        float4 xr[4];
        if (more) {
            #pragma unroll
            for (int r = 0; r < 2; ++r) {
                int ch = wc16 + r * 4;
                int g = wbase + (k0 + 32 + wrow) * HH + ch * 8;
                uint32_t d = stn + (warr ? OWL : OWH) + wrow * WSTRB + ch * 16;
                cp_async16(d, warr ? (const void*)&g_Wl[g] : (const void*)&g_Wh[g]);
            }
            CP_COMMIT();
            #pragma unroll
            for (int r = 0; r < 4; ++r) {
                int idx = t + r * 256;
                int row = idx >> 3, c4 = idx & 7;
                xr[r] = *(const float4*)&X[(size_t)(row0 + row) * CC + k0 + 32 + c4 * 4];
            }
        }

        // ---- MMA on current stage ----
        #pragma unroll
        for (int ks = 0; ks < 2; ++ks) {
            uint32_t ah[2][4], al[2][4];
            #pragma unroll
            for (int mf = 0; mf < 2; ++mf) {
                uint32_t addr = stc + (mw * 32 + mf * 16 + rAo) * XSTRB + (ks * 2 + cAo) * 16;
                ldsm_x4(ah[mf][0], ah[mf][1], ah[mf][2], ah[mf][3], addr + OXH);
                ldsm_x4(al[mf][0], al[mf][1], al[mf][2], al[mf][3], addr + OXL);
            }
            uint32_t bh[4][2], bl[4][2];
            #pragma unroll
            for (int nn = 0; nn < 2; ++nn) {
                uint32_t addr = stc + (ks * 16 + rBo) * WSTRB + (nw * 4 + nn * 2 + cBo) * 16;
                uint32_t h0, h1, h2, h3, l0_, l1_, l2_, l3_;
                ldsm_x4t(h0, h1, h2, h3, addr + OWH);
                ldsm_x4t(l0_, l1_, l2_, l3_, addr + OWL);
                bh[nn*2][0] = h0; bh[nn*2][1] = h1;
                bh[nn*2+1][0] = h2; bh[nn*2+1][1] = h3;
                bl[nn*2][0] = l0_; bl[nn*2][1] = l1_;
                bl[nn*2+1][0] = l2_; bl[nn*2+1][1] = l3_;
            }
            #pragma unroll
            for (int mf = 0; mf < 2; ++mf)
                #pragma unroll
                for (int nf = 0; nf < 4; ++nf) {
                    mma_bf16(c[mf][nf], ah[mf], bh[nf][0], bh[nf][1]);
                    mma_bf16(c[mf][nf], ah[mf], bl[nf][0], bl[nf][1]);
                    mma_bf16(c[mf][nf], al[mf], bh[nf][0], bh[nf][1]);
                }
        }

        if (more) {
            #pragma unroll
            for (int r = 0; r < 4; ++r) {
                int idx = t + r * 256;
                int row = idx >> 3, c4 = idx & 7;
                uint32_t h0, l0, h1, l1;
                split2(xr[r].x, xr[r].y, h0, l0);
                split2(xr[r].z, xr[r].w, h1, l1);
                *(uint2*)(pnx + OXH + row * XSTRB + c4 * 8) = make_uint2(h0, h1);
                *(uint2*)(pnx + OXL + row * XSTRB + c4 * 8) = make_uint2(l0, l1);
            }
        }
    }

    // ---- epilogue: split-store to bf16 hi/lo outputs ----
    __nv_bfloat16 *oh, *ol;
    float sc = 1.0f;
    switch (sel) {
        case 0:  oh = g_Kh; ol = g_Kl; break;
        case 1:  oh = g_Qh; ol = g_Ql; sc = 0.08838834764831845f; break;
        default: oh = g_Vh; ol = g_Vl; break;
    }
    #pragma unroll
    for (int mf = 0; mf < 2; ++mf) {
        #pragma unroll
        for (int nf = 0; nf < 4; ++nf) {
            int row = row0 + mw * 32 + mf * 16 + (lane >> 2);
            int col = nh * 64 + nw * 32 + nf * 8 + (lane & 3) * 2;
            uint32_t h, l;
            split2(c[mf][nf][0] * sc, c[mf][nf][1] * sc, h, l);
            *(uint32_t*)&oh[(size_t)row * HH + col] = h;
            *(uint32_t*)&ol[(size_t)row * HH + col] = l;
            split2(c[mf][nf][2] * sc, c[mf][nf][3] * sc, h, l);
            *(uint32_t*)&oh[(size_t)(row + 8) * HH + col] = h;
            *(uint32_t*)&ol[(size_t)(row + 8) * HH + col] = l;
        }
    }
}

// ------------------------------------------------------------------
// Stage 2: flash attention (R7 version, known-good: 215.6us total).
// ------------------------------------------------------------------
#define SWZ(r,c) (((r) << 8) | ((((c) ^ ((r) & 7))) << 4))
#define AST 65536
#define ATTN_SMEM_BYTES (2*AST)

__global__ __launch_bounds__(128) void attn_kernel(float* __restrict__ out)
{
    extern __shared__ __align__(16) unsigned char smraw[];
    const int t = threadIdx.x, lane = t & 31, w = t >> 5;
    const int bid = blockIdx.x;
    const int b  = bid & 7;
    const int qt = 31 - (bid >> 3);
    const int q0 = qt * 64;
    const uint32_t sb = (uint32_t)__cvta_generic_to_shared(smraw);

    #pragma unroll
    for (int r = 0; r < 8; ++r) {
        int idx = t + r * 128;
        int row = idx >> 4, c = idx & 15;
        int g  = (b * TT + row) * HH + c * 8;
        int sw = SWZ(row, c);
        cp_async16(sb +         sw, &g_Kh[g]);
        cp_async16(sb + 16384 + sw, &g_Kl[g]);
        cp_async16(sb + 32768 + sw, &g_Vh[g]);
        cp_async16(sb + 49152 + sw, &g_Vl[g]);
    }
    CP_COMMIT();

    #pragma unroll
    for (int r = 0; r < 8; ++r) {
        int idx = t + r * 128;
        int row = idx >> 4, c = idx & 15;
        int g = (b * TT + q0 + row) * HH + c * 8;
        *(uint4*)(smraw + AST +         SWZ(row, c)) = *(const uint4*)&g_Qh[g];
        *(uint4*)(smraw + AST + 16384 + SWZ(row, c)) = *(const uint4*)&g_Ql[g];
    }
    __syncthreads();

    uint32_t qh[8][4], ql[8][4];
    {
        int tQ  = lane >> 3;
        int rA  = w * 16 + (lane & 7) + ((tQ & 1) << 3);
        int cOf = tQ >> 1;
        #pragma unroll
        for (int ks = 0; ks < 8; ++ks) {
            int c = ks * 2 + cOf;
            ldsm_x4(qh[ks][0], qh[ks][1], qh[ks][2], qh[ks][3], sb + AST +         SWZ(rA, c));
            ldsm_x4(ql[ks][0], ql[ks][1], ql[ks][2], ql[ks][3], sb + AST + 16384 + SWZ(rA, c));
        }
    }

    float o[16][4];
    #pragma unroll
    for (int i = 0; i < 16; ++i)
        #pragma unroll
        for (int j = 0; j < 4; ++j) o[i][j] = 0.f;
    float m0 = -1e30f, m1 = -1e30f, l0 = 0.f, l1 = 0.f;

    const int tK  = lane >> 3;
    const int rB  = (lane & 7) + ((tK >> 1) << 3);
    const int cB  = tK & 1;
    const int rVo = (lane & 7) + ((tK & 1) << 3);
    const int cVo = tK >> 1;

    for (int kt = 0; kt <= qt; ++kt) {
        const uint32_t stc = sb + (uint32_t)(kt & 1) * AST;

        CP_WAIT0();
        __syncthreads();

        if (kt < qt) {
            const uint32_t stn = sb + (uint32_t)((kt + 1) & 1) * AST;
            #pragma unroll
            for (int r = 0; r < 8; ++r) {
                int idx = t + r * 128;
                int row = idx >> 4, c = idx & 15;
                int g  = (b * TT + (kt + 1) * 64 + row) * HH + c * 8;
                int sw = SWZ(row, c);
                cp_async16(stn +         sw, &g_Kh[g]);
                cp_async16(stn + 16384 + sw, &g_Kl[g]);
                cp_async16(stn + 32768 + sw, &g_Vh[g]);
                cp_async16(stn + 49152 + sw, &g_Vl[g]);
            }
            CP_COMMIT();
        }

        float s[8][4];
        #pragma unroll
        for (int i = 0; i < 8; ++i)
            #pragma unroll
            for (int j = 0; j < 4; ++j) s[i][j] = 0.f;

        #pragma unroll
        for (int ks = 0; ks < 8; ++ks) {
            #pragma unroll
            for (int p = 0; p < 4; ++p) {
                int rr = p * 16 + rB;
                int cc = ks * 2 + cB;
                uint32_t bh0, bh1, bh2, bh3, bl0, bl1, bl2, bl3;
                ldsm_x4(bh0, bh1, bh2, bh3, stc +         SWZ(rr, cc));
                ldsm_x4(bl0, bl1, bl2, bl3, stc + 16384 + SWZ(rr, cc));
                mma_bf16(s[2*p],     qh[ks], bh0, bh1);
                mma_bf16(s[2*p],     qh[ks], bl0, bl1);
                mma_bf16(s[2*p],     ql[ks], bh0, bh1);
                mma_bf16(s[2*p + 1], qh[ks], bh2, bh3);
                mma_bf16(s[2*p + 1], qh[ks], bl2, bl3);
                mma_bf16(s[2*p + 1], ql[ks], bh2, bh3);
            }
        }

        if (kt == qt) {
            int row0 = w * 16 + (lane >> 2);
            int colb = 2 * (lane & 3);
            #pragma unroll
            for (int nf = 0; nf < 8; ++nf) {
                int cA = nf * 8 + colb;
                if (cA     > row0)     s[nf][0] = -1e30f;
                if (cA + 1 > row0)     s[nf][1] = -1e30f;
                if (cA     > row0 + 8) s[nf][2] = -1e30f;
                if (cA + 1 > row0 + 8) s[nf][3] = -1e30f;
            }
        }

        float mx0 = -1e30f, mx1 = -1e30f;
        #pragma unroll
        for (int nf = 0; nf < 8; ++nf) {
            mx0 = fmaxf(mx0, fmaxf(s[nf][0], s[nf][1]));
            mx1 = fmaxf(mx1, fmaxf(s[nf][2], s[nf][3]));
        }
        mx0 = fmaxf(mx0, __shfl_xor_sync(0xffffffffu, mx0, 1));
        mx0 = fmaxf(mx0, __shfl_xor_sync(0xffffffffu, mx0, 2));
        mx1 = fmaxf(mx1, __shfl_xor_sync(0xffffffffu, mx1, 1));
        mx1 = fmaxf(mx1, __shfl_xor_sync(0xffffffffu, mx1, 2));
        float mn0 = fmaxf(m0, mx0), mn1 = fmaxf(m1, mx1);
        float a0 = __expf(m0 - mn0), a1 = __expf(m1 - mn1);
        m0 = mn0; m1 = mn1;
        float ls0 = 0.f, ls1 = 0.f;
        #pragma unroll
        for (int nf = 0; nf < 8; ++nf) {
            s[nf][0] = __expf(s[nf][0] - mn0); ls0 += s[nf][0];
            s[nf][1] = __expf(s[nf][1] - mn0); ls0 += s[nf][1];
            s[nf][2] = __expf(s[nf][2] - mn1); ls1 += s[nf][2];
            s[nf][3] = __expf(s[nf][3] - mn1); ls1 += s[nf][3];
        }
        ls0 += __shfl_xor_sync(0xffffffffu, ls0, 1);
        ls0 += __shfl_xor_sync(0xffffffffu, ls0, 2);
        ls1 += __shfl_xor_sync(0xffffffffu, ls1, 1);
        ls1 += __shfl_xor_sync(0xffffffffu, ls1, 2);
        l0 = l0 * a0 + ls0;
        l1 = l1 * a1 + ls1;

        #pragma unroll
        for (int nd = 0; nd < 16; ++nd) {
            o[nd][0] *= a0; o[nd][1] *= a0;
            o[nd][2] *= a1; o[nd][3] *= a1;
        }

        uint32_t ph[4][4], pl[4][4];
        #pragma unroll
        for (int kp = 0; kp < 4; ++kp) {
            int nfA = 2 * kp, nfB = 2 * kp + 1;
            split2(s[nfA][0], s[nfA][1], ph[kp][0], pl[kp][0]);
            split2(s[nfA][2], s[nfA][3], ph[kp][1], pl[kp][1]);
            split2(s[nfB][0], s[nfB][1], ph[kp][2], pl[kp][2]);
            split2(s[nfB][2], s[nfB][3], ph[kp][3], pl[kp][3]);
        }

        #pragma unroll
        for (int kp = 0; kp < 4; ++kp) {
            #pragma unroll
            for (int np = 0; np < 8; ++np) {
                int rV = kp * 16 + rVo;
                int cV = np * 2 + cVo;
                uint32_t vh0, vh1, vh2, vh3, vl0, vl1, vl2, vl3;
                ldsm_x4t(vh0, vh1, vh2, vh3, stc + 32768 + SWZ(rV, cV));
                ldsm_x4t(vl0, vl1, vl2, vl3, stc + 49152 + SWZ(rV, cV));
                mma_bf16(o[2*np],     ph[kp], vh0, vh1);
                mma_bf16(o[2*np],     ph[kp], vl0, vl1);
                mma_bf16(o[2*np],     pl[kp], vh0, vh1);
                mma_bf16(o[2*np + 1], ph[kp], vh2, vh3);
                mma_bf16(o[2*np + 1], ph[kp], vl2, vl3);
                mma_bf16(o[2*np + 1], pl[kp], vh2, vh3);
            }
        }
    }

    {
        int grow0 = q0 + w * 16 + (lane >> 2);
        float i0 = 1.0f / l0, i1 = 1.0f / l1;
        #pragma unroll
        for (int nd = 0; nd < 16; ++nd) {
            int col = nd * 8 + 2 * (lane & 3);
            float2 v0 = make_float2(o[nd][0] * i0, o[nd][1] * i0);
            float2 v1 = make_float2(o[nd][2] * i1, o[nd][3] * i1);
            *(float2*)&out[(size_t)(b * TT + grow0) * HH + col]       = v0;
            *(float2*)&out[(size_t)(b * TT + grow0 + 8) * HH + col]   = v1;
        }
    }
}

// ------------------------------------------------------------------
extern "C" void kernel_launch(void* const* d_in, const int* in_sizes, int n_in,
                              void* d_out, int out_size)
{
    const float* x  = (const float*)d_in[0];
    const float* Wk = (const float*)d_in[1];
    const float* Wq = (const float*)d_in[2];
    const float* Wv = (const float*)d_in[3];
    float* out = (float*)d_out;

    (void)in_sizes; (void)n_in; (void)out_size;

    cudaFuncSetAttribute(qkv_mma_kernel,
                         cudaFuncAttributeMaxDynamicSharedMemorySize,
                         QKV_SMEM);
    cudaFuncSetAttribute(attn_kernel,
                         cudaFuncAttributeMaxDynamicSharedMemorySize,
                         ATTN_SMEM_BYTES);

    split_w_kernel<<<dim3(CC * HH / 4 / 256, 3), 256>>>(Wk, Wq, Wv);
    qkv_mma_kernel<<<dim3(BB * TT / 128, 6), 256, QKV_SMEM>>>(x);
    attn_kernel<<<dim3(TT / 64 * BB), 128, ATTN_SMEM_BYTES>>>(out);
}